// round 16
// baseline (speedup 1.0000x reference)
#include <cuda_runtime.h>
#include <cuda_fp16.h>
#include <math.h>
#include <stdint.h>

#define BB 2
#define SS 2048
#define DD 1024
#define HH 16
#define DK 64
#define OUT_ELEMS (BB * SS * DD)
#define ATT_ELEMS ((long long)BB * HH * SS * (long long)SS)

// ---------------- scratch (allocation-free rule) ----------------
__device__ __align__(16) __half g_in[3][4194304];
__device__ __align__(16) __half g_w_h[4][1048576], g_w_l[4][1048576];
__device__ __align__(16) __half g_qh[4194304];
__device__ __align__(16) __half g_kh[4194304];      // K heads hi-only
__device__ __align__(16) __half g_vt[4194304];      // V^T hi-only
__device__ __align__(16) __half g_ctx[4194304];

// ---------------- PTX helpers ----------------
__device__ __forceinline__ uint32_t smem_u32(const void* p) {
    return (uint32_t)__cvta_generic_to_shared(p);
}
__device__ __forceinline__ void ldm_x4(uint32_t* r, uint32_t addr) {
    asm volatile("ldmatrix.sync.aligned.m8n8.x4.shared.b16 {%0,%1,%2,%3}, [%4];\n"
                 : "=r"(r[0]), "=r"(r[1]), "=r"(r[2]), "=r"(r[3]) : "r"(addr));
}
__device__ __forceinline__ void mma16816(float* d, const uint32_t* a,
                                         uint32_t b0, uint32_t b1) {
    asm volatile(
        "mma.sync.aligned.m16n8k16.row.col.f32.f16.f16.f32 "
        "{%0,%1,%2,%3}, {%4,%5,%6,%7}, {%8,%9}, {%0,%1,%2,%3};\n"
        : "+f"(d[0]), "+f"(d[1]), "+f"(d[2]), "+f"(d[3])
        : "r"(a[0]), "r"(a[1]), "r"(a[2]), "r"(a[3]), "r"(b0), "r"(b1));
}
__device__ __forceinline__ void split2h(float x, __half& h, __half& l) {
    h = __float2half(x);
    l = __float2half(x - __half2float(h));
}
__device__ __forceinline__ void cp16(uint32_t dst, const void* src) {
    asm volatile("cp.async.cg.shared.global [%0], [%1], 16;\n" :: "r"(dst), "l"(src));
}
__device__ __forceinline__ void cp_commit() { asm volatile("cp.async.commit_group;\n"); }
__device__ __forceinline__ void cp_wait0() { asm volatile("cp.async.wait_group 0;\n" ::: "memory"); }

// ---------------------------------------------------------------------------
// Convert fp32 sources (grid-stride). Inputs: fp16 plain. Weights: hi/lo.
// grid = (1024, 7).
// ---------------------------------------------------------------------------
__global__ __launch_bounds__(256) void convert_all(
    const float* __restrict__ Q, const float* __restrict__ K,
    const float* __restrict__ V, const float* __restrict__ WQ,
    const float* __restrict__ WK, const float* __restrict__ WV,
    const float* __restrict__ WO)
{
    const int seg = blockIdx.y;
    const int nf4 = (seg < 3) ? (4194304 / 4) : (1048576 / 4);
    if (seg < 3) {
        const float* src = (seg == 0) ? Q : (seg == 1) ? K : V;
        __half* dh = g_in[seg];
        for (int i = blockIdx.x * 256 + threadIdx.x; i < nf4; i += 1024 * 256) {
            float4 v = ((const float4*)src)[i];
            ((__half2*)dh)[i * 2 + 0] = __floats2half2_rn(v.x, v.y);
            ((__half2*)dh)[i * 2 + 1] = __floats2half2_rn(v.z, v.w);
        }
    } else {
        const int w = seg - 3;
        const float* src = (w == 0) ? WQ : (w == 1) ? WK : (w == 2) ? WV : WO;
        __half *dh = g_w_h[w], *dl = g_w_l[w];
        for (int i = blockIdx.x * 256 + threadIdx.x; i < nf4; i += 1024 * 256) {
            float4 v = ((const float4*)src)[i];
            __half h0, l0, h1, l1, h2, l2, h3, l3;
            split2h(v.x, h0, l0); split2h(v.y, h1, l1);
            split2h(v.z, h2, l2); split2h(v.w, h3, l3);
            ((__half2*)dh)[i * 2 + 0] = __halves2half2(h0, h1);
            ((__half2*)dh)[i * 2 + 1] = __halves2half2(h2, h3);
            ((__half2*)dl)[i * 2 + 0] = __halves2half2(l0, l1);
            ((__half2*)dl)[i * 2 + 1] = __halves2half2(l2, l3);
        }
    }
}

// ---------------------------------------------------------------------------
// Projection GEMM: out = A @ B^T + bias. A plain fp16, B hi/lo fp16.
// BK=64, 2-stage cp.async, 128x128 tile, 8 warps (4m x 2n). [R15 proven]
// z: 0=Q (scaled, hi-only), 1=K (hi-only), 2=V (V^T hi-only), 3=O (fp32).
// ---------------------------------------------------------------------------
#define PPAD 72
#define PTILE (128 * PPAD)
#define PSTAGE (3 * PTILE)
#define PROJ_SMEM (2 * PSTAGE * (int)sizeof(__half))  // 110592

__device__ __forceinline__ void proj_issue(
    __half* ps, int stage,
    const __half* A_, const __half* Bh_, const __half* Bl_,
    int bm, int bn, int kt, int tid)
{
    __half* base = ps + stage * PSTAGE;
#pragma unroll
    for (int t = 0; t < 12; t++) {
        const int idx = tid + t * 256;
        const int arr = idx >> 10;
        const int row = (idx >> 3) & 127;
        const int ch = idx & 7;
        const __half* g;
        if (arr == 0)      g = A_  + (size_t)(bm * 128 + row) * 1024 + kt + ch * 8;
        else if (arr == 1) g = Bh_ + (size_t)(bn * 128 + row) * 1024 + kt + ch * 8;
        else               g = Bl_ + (size_t)(bn * 128 + row) * 1024 + kt + ch * 8;
        cp16(smem_u32(base + arr * PTILE + row * PPAD + ch * 8), g);
    }
    cp_commit();
}

__global__ __launch_bounds__(256, 2) void proj_gemm(
    const __half* __restrict__ in0, const __half* __restrict__ in1,
    const __half* __restrict__ in2, const __half* __restrict__ ctx,
    const __half* __restrict__ wh, const __half* __restrict__ wl,
    const float* __restrict__ bQ, const float* __restrict__ bK,
    const float* __restrict__ bV, const float* __restrict__ bO,
    float* __restrict__ outO,
    __half* __restrict__ qh, __half* __restrict__ kh,
    __half* __restrict__ vt,
    int which)
{
    extern __shared__ __half ps[];
    const int tid = threadIdx.x, lane = tid & 31, wid = tid >> 5;
    const int wm = wid >> 1, wn = wid & 1;
    const int bm = blockIdx.y, bn = blockIdx.x;
    const int z = (which >= 0) ? which : (int)blockIdx.z;

    const __half *A_, *Bh_, *Bl_;
    const float* bias;
    __half* oh = nullptr;
    int mode; float scale = 1.0f;
    if (z == 0)      { A_ = in0; Bh_ = wh; Bl_ = wl; bias = bQ; mode = 1;
                       oh = qh; scale = 0.125f * 1.4426950408889634f; }
    else if (z == 1) { A_ = in1; Bh_ = wh + 1048576; Bl_ = wl + 1048576;
                       bias = bK; mode = 1; oh = kh; }
    else if (z == 2) { A_ = in2; Bh_ = wh + 2 * 1048576; Bl_ = wl + 2 * 1048576;
                       bias = bV; mode = 3; }
    else             { A_ = ctx; Bh_ = wh + 3 * 1048576; Bl_ = wl + 3 * 1048576;
                       bias = bO; mode = 0; }

    float acc[2][8][4];
#pragma unroll
    for (int m = 0; m < 2; m++)
#pragma unroll
        for (int n = 0; n < 8; n++)
#pragma unroll
            for (int k = 0; k < 4; k++) acc[m][n][k] = 0.0f;

    proj_issue(ps, 0, A_, Bh_, Bl_, bm, bn, 0, tid);

    for (int kt = 0; kt < 1024; kt += 64) {
        const int s = (kt >> 6) & 1;
        cp_wait0();
        __syncthreads();
        if (kt + 64 < 1024)
            proj_issue(ps, s ^ 1, A_, Bh_, Bl_, bm, bn, kt + 64, tid);

        __half* Ah = ps + s * PSTAGE;
        __half* Bh = Ah + PTILE;
        __half* Bl = Bh + PTILE;

#pragma unroll
        for (int kk = 0; kk < 64; kk += 16) {
            uint32_t ah[2][4];
#pragma unroll
            for (int mt = 0; mt < 2; mt++) {
                const int r = wm * 32 + mt * 16 + (lane & 15);
                const int c = kk + (lane >> 4) * 8;
                ldm_x4(ah[mt], smem_u32(&Ah[r * PPAD + c]));
            }
#pragma unroll
            for (int nt = 0; nt < 4; nt++) {
                uint32_t bh[4], bl[4];
                const int r = wn * 64 + nt * 16 + (lane & 15);
                const int c = kk + (lane >> 4) * 8;
                ldm_x4(bh, smem_u32(&Bh[r * PPAD + c]));
                ldm_x4(bl, smem_u32(&Bl[r * PPAD + c]));
#pragma unroll
                for (int mt = 0; mt < 2; mt++) {
                    mma16816(acc[mt][nt * 2 + 0], ah[mt], bh[0], bh[2]);
                    mma16816(acc[mt][nt * 2 + 1], ah[mt], bh[1], bh[3]);
                    mma16816(acc[mt][nt * 2 + 0], ah[mt], bl[0], bl[2]);
                    mma16816(acc[mt][nt * 2 + 1], ah[mt], bl[1], bl[3]);
                }
            }
        }
    }

#pragma unroll
    for (int mt = 0; mt < 2; mt++) {
#pragma unroll
        for (int n8 = 0; n8 < 8; n8++) {
            const int r0 = bm * 128 + wm * 32 + mt * 16 + (lane >> 2);
            const int c  = bn * 128 + wn * 64 + n8 * 8 + (lane & 3) * 2;
            const float b0 = bias[c], b1 = bias[c + 1];
#pragma unroll
            for (int half_ = 0; half_ < 2; half_++) {
                const int r = r0 + half_ * 8;
                const float v0 = (acc[mt][n8][half_ * 2 + 0] + b0) * scale;
                const float v1 = (acc[mt][n8][half_ * 2 + 1] + b1) * scale;
                const int bb = r >> 11, sidx = r & 2047;
                const int hh = c >> 6, dk = c & 63;
                if (mode == 0) {
                    *(float2*)&outO[(size_t)r * DD + c] = make_float2(v0, v1);
                } else if (mode == 1) {
                    const size_t a = ((size_t)(bb * HH + hh) * SS + sidx) * DK + dk;
                    *(__half2*)&oh[a] = __floats2half2_rn(v0, v1);
                } else {
                    const size_t a = ((size_t)(bb * HH + hh) * DK + dk) * SS + sidx;
                    vt[a] = __float2half(v0);
                    vt[a + SS] = __float2half(v1);
                }
            }
        }
    }
}

// ---------------------------------------------------------------------------
// Attention: q-tile 128, 256 threads (8 warps in q). Two-pass, hi-only scores
// and hi-only V, P kept in registers. k-tiles STAGED 128 wide, computed as two
// 64-wide sub-tiles (same registers, half the barriers).
// ---------------------------------------------------------------------------
#define QT 128
#define KPAD 72
#define VPAD 136
#define KTILE (128 * KPAD)       // 9216 halves
#define VTILE (64 * VPAD)        // 8704 halves
#define ASTG (KTILE + VTILE)     // 17920 halves
#define ATT_SMEM ((2 * ASTG + 128 * KPAD) * (int)sizeof(__half))  // 90112

// pass A: Kh (128 k-rows x 64 dk) only
__device__ __forceinline__ void attn_issueKh(
    __half* sm, int stage, const __half* Kh_, int bh, int k0, int tid)
{
    __half* base = sm + stage * ASTG;
#pragma unroll
    for (int t = 0; t < 4; t++) {
        const int idx = tid + t * 256;
        const int row = idx >> 3, ch = idx & 7;
        const __half* g = Kh_ + ((size_t)bh * SS + k0 + row) * DK + ch * 8;
        cp16(smem_u32(base + row * KPAD + ch * 8), g);
    }
    cp_commit();
}

// pass B: Kh + V^T (64 dk-rows x 128 s-cols)
__device__ __forceinline__ void attn_issueKV(
    __half* sm, int stage, const __half* Kh_, const __half* Vt_,
    int bh, int k0, int tid)
{
    __half* base = sm + stage * ASTG;
#pragma unroll
    for (int t = 0; t < 8; t++) {
        const int idx = tid + t * 256;
        if (idx < 1024) {
            const int row = idx >> 3, ch = idx & 7;
            const __half* g = Kh_ + ((size_t)bh * SS + k0 + row) * DK + ch * 8;
            cp16(smem_u32(base + row * KPAD + ch * 8), g);
        } else {
            const int j = idx - 1024;
            const int row = j >> 4, ch = j & 15;
            const __half* g = Vt_ + ((size_t)bh * DK + row) * SS + k0 + ch * 8;
            cp16(smem_u32(base + KTILE + row * VPAD + ch * 8), g);
        }
    }
    cp_commit();
}

__global__ __launch_bounds__(256, 2) void attn_mma(
    const __half* __restrict__ Qh_,
    const __half* __restrict__ Kh_,
    const __half* __restrict__ Vt_,
    __half* __restrict__ ctx,
    float* __restrict__ attn_out, int write_attn)
{
    extern __shared__ __half sm[];
    __half* Ph = sm + 2 * ASTG;   // Q staging, 128 x KPAD

    const int tid = threadIdx.x, lane = tid & 31, wid = tid >> 5;
    const int b = blockIdx.z, h = blockIdx.y, bh = b * HH + h;
    const int q0 = ((int)gridDim.x - 1 - (int)blockIdx.x) * QT;  // longest first

    // ---- prologue: Q tile (hi only) -> Ph, K tile 0 -> stage 0 ----
#pragma unroll
    for (int t = 0; t < 4; t++) {
        const int idx = tid + t * 256;
        const int row = (idx >> 3) & 127, ch = idx & 7;
        const __half* g = Qh_ + ((size_t)bh * SS + q0 + row) * DK + ch * 8;
        cp16(smem_u32(Ph + row * KPAD + ch * 8), g);
    }
    cp_commit();
    attn_issueKh(sm, 0, Kh_, bh, 0, tid);
    cp_wait0();
    __syncthreads();

    uint32_t qf[4][4];
#pragma unroll
    for (int kk = 0; kk < 4; kk++) {
        const int r = wid * 16 + (lane & 15);
        const int c = kk * 16 + (lane >> 4) * 8;
        ldm_x4(qf[kk], smem_u32(&Ph[r * KPAD + c]));
    }
    __syncthreads();

    const int qr0 = q0 + wid * 16 + (lane >> 2);
    const int qmaxw = q0 + wid * 16 + 15;
    const int kend = q0 + 64;   // last 64-sub-tile start
    float lacc0 = 0.0f, lacc1 = 0.0f;

    // ================= PASS A: row sums (K-hi only) =================
    for (int k0 = 0; k0 <= kend; k0 += 128) {
        const int s = (k0 >> 7) & 1;
        cp_wait0();
        __syncthreads();
        if (k0 + 128 <= kend)
            attn_issueKh(sm, s ^ 1, Kh_, bh, k0 + 128, tid);

#pragma unroll
        for (int sub = 0; sub < 2; sub++) {
            const int k0s = k0 + sub * 64;
            if (k0s > kend) break;
            if (k0s > qmaxw) continue;
            __half* Kh = sm + s * ASTG + sub * 64 * KPAD;

            float sa[8][4];
#pragma unroll
            for (int f = 0; f < 8; f++)
#pragma unroll
                for (int k = 0; k < 4; k++) sa[f][k] = 0.0f;

#pragma unroll
            for (int kk = 0; kk < 4; kk++) {
#pragma unroll
                for (int nt = 0; nt < 4; nt++) {
                    uint32_t bhf[4];
                    const int r = nt * 16 + (lane & 15);
                    const int c = kk * 16 + (lane >> 4) * 8;
                    ldm_x4(bhf, smem_u32(&Kh[r * KPAD + c]));
                    mma16816(sa[nt * 2 + 0], qf[kk], bhf[0], bhf[2]);
                    mma16816(sa[nt * 2 + 1], qf[kk], bhf[1], bhf[3]);
                }
            }

            const bool diag = (k0s + 63 > q0 + wid * 16);
#pragma unroll
            for (int f = 0; f < 8; f++) {
                const int jc = k0s + (f >> 1) * 16 + (f & 1) * 8 + (lane & 3) * 2;
#pragma unroll
                for (int half_ = 0; half_ < 2; half_++) {
                    const int qr = qr0 + half_ * 8;
                    float p0 = exp2f(sa[f][half_ * 2 + 0]);
                    float p1 = exp2f(sa[f][half_ * 2 + 1]);
                    if (diag) {
                        if (jc + 0 > qr) p0 = 0.0f;
                        if (jc + 1 > qr) p1 = 0.0f;
                    }
                    if (half_ == 0) lacc0 += p0 + p1; else lacc1 += p0 + p1;
                }
            }
        }
    }

    lacc0 += __shfl_xor_sync(0xffffffffu, lacc0, 1);
    lacc0 += __shfl_xor_sync(0xffffffffu, lacc0, 2);
    lacc1 += __shfl_xor_sync(0xffffffffu, lacc1, 1);
    lacc1 += __shfl_xor_sync(0xffffffffu, lacc1, 2);
    const float inv0 = 1.0f / lacc0;
    const float inv1 = 1.0f / lacc1;

    float ctxa[8][4];
#pragma unroll
    for (int f = 0; f < 8; f++)
#pragma unroll
        for (int k = 0; k < 4; k++) ctxa[f][k] = 0.0f;

    // ================= PASS B: normalized attn + PV =================
    cp_wait0();
    __syncthreads();
    attn_issueKV(sm, 0, Kh_, Vt_, bh, 0, tid);

    for (int k0 = 0; k0 <= kend; k0 += 128) {
        const int s = (k0 >> 7) & 1;
        cp_wait0();
        __syncthreads();
        if (k0 + 128 <= kend)
            attn_issueKV(sm, s ^ 1, Kh_, Vt_, bh, k0 + 128, tid);

#pragma unroll
        for (int sub = 0; sub < 2; sub++) {
            const int k0s = k0 + sub * 64;
            if (k0s > kend) break;

            if (k0s > qmaxw) {
                if (write_attn) {
#pragma unroll
                    for (int f = 0; f < 8; f++) {
                        const int jc = k0s + (f >> 1) * 16 + (f & 1) * 8 + (lane & 3) * 2;
#pragma unroll
                        for (int half_ = 0; half_ < 2; half_++) {
                            const int qr = qr0 + half_ * 8;
                            const size_t grow = (size_t)(bh * SS + qr);
                            *(float2*)&attn_out[grow * SS + jc] = make_float2(0.f, 0.f);
                        }
                    }
                }
                continue;
            }

            __half* Kh = sm + s * ASTG + sub * 64 * KPAD;
            __half* Vh = sm + s * ASTG + KTILE + sub * 64;

            float sa[8][4];
#pragma unroll
            for (int f = 0; f < 8; f++)
#pragma unroll
                for (int k = 0; k < 4; k++) sa[f][k] = 0.0f;

#pragma unroll
            for (int kk = 0; kk < 4; kk++) {
#pragma unroll
                for (int nt = 0; nt < 4; nt++) {
                    uint32_t bhf[4];
                    const int r = nt * 16 + (lane & 15);
                    const int c = kk * 16 + (lane >> 4) * 8;
                    ldm_x4(bhf, smem_u32(&Kh[r * KPAD + c]));
                    mma16816(sa[nt * 2 + 0], qf[kk], bhf[0], bhf[2]);
                    mma16816(sa[nt * 2 + 1], qf[kk], bhf[1], bhf[3]);
                }
            }

            const bool diag = (k0s + 63 > q0 + wid * 16);
            uint32_t pa[4][4];
#pragma unroll
            for (int f = 0; f < 8; f++) {
                const int jc = k0s + (f >> 1) * 16 + (f & 1) * 8 + (lane & 3) * 2;
#pragma unroll
                for (int half_ = 0; half_ < 2; half_++) {
                    const int qr = qr0 + half_ * 8;
                    const float iv = half_ ? inv1 : inv0;
                    float p0 = exp2f(sa[f][half_ * 2 + 0]) * iv;
                    float p1 = exp2f(sa[f][half_ * 2 + 1]) * iv;
                    if (diag) {
                        if (jc + 0 > qr) p0 = 0.0f;
                        if (jc + 1 > qr) p1 = 0.0f;
                    }
                    if (write_attn) {
                        const size_t grow = (size_t)(bh * SS + qr);
                        *(float2*)&attn_out[grow * SS + jc] = make_float2(p0, p1);
                    }
                    __half2 ph2 = __floats2half2_rn(p0, p1);
                    pa[f >> 1][(f & 1) * 2 + half_] = *(uint32_t*)&ph2;
                }
            }

            // ---- ctx += P V (V hi-only) ----
#pragma unroll
            for (int kk = 0; kk < 4; kk++) {
#pragma unroll
                for (int nt = 0; nt < 4; nt++) {
                    uint32_t vh_[4];
                    const int r = nt * 16 + (lane & 15);
                    const int c = kk * 16 + (lane >> 4) * 8;
                    ldm_x4(vh_, smem_u32(&Vh[r * VPAD + c]));
                    mma16816(ctxa[nt * 2 + 0], pa[kk], vh_[0], vh_[2]);
                    mma16816(ctxa[nt * 2 + 1], pa[kk], vh_[1], vh_[3]);
                }
            }
        }
    }

    // ---- ctx write (concat layout), plain fp16 ----
    const int qloc = wid * 16 + (lane >> 2);
#pragma unroll
    for (int f = 0; f < 8; f++) {
        const int dc = (f >> 1) * 16 + (f & 1) * 8 + (lane & 3) * 2;
        const size_t r0 = (size_t)(b * SS + q0 + qloc);
        *(__half2*)&ctx[r0 * DD + h * DK + dc] =
            __floats2half2_rn(ctxa[f][0], ctxa[f][1]);
        *(__half2*)&ctx[(r0 + 8) * DD + h * DK + dc] =
            __floats2half2_rn(ctxa[f][2], ctxa[f][3]);
    }

    // ---- zero-fill columns [q0+QT, SS) for these QT rows ----
    if (write_attn) {
        const int zstart = q0 + QT;
        const int zw = SS - zstart;
        if (zw > 0) {
            const int n4 = zw >> 2;
            const size_t base = (size_t)bh * SS * SS;
            const float4 z = make_float4(0.f, 0.f, 0.f, 0.f);
            for (int i = tid; i < QT * n4; i += 256) {
                const int r = i / n4;
                const int cc = (i - r * n4) << 2;
                *(float4*)&attn_out[base + (size_t)(q0 + r) * SS + zstart + cc] = z;
            }
        }
    }
}

// ---------------------------------------------------------------------------
extern "C" void kernel_launch(void* const* d_in, const int* in_sizes, int n_in,
                              void* d_out, int out_size)
{
    const float* Q  = (const float*)d_in[0];
    const float* K  = (const float*)d_in[1];
    const float* V  = (const float*)d_in[2];
    // d_in[3] = causal mask (fixed) — handled analytically
    const float* WQ = (const float*)d_in[4];
    const float* bQ = (const float*)d_in[5];
    const float* WK = (const float*)d_in[6];
    const float* bK = (const float*)d_in[7];
    const float* WV = (const float*)d_in[8];
    const float* bV = (const float*)d_in[9];
    const float* WO = (const float*)d_in[10];
    const float* bO = (const float*)d_in[11];

    __half *in0, *wh, *wl, *qh, *kh, *vt, *ctx;
    cudaGetSymbolAddress((void**)&in0, g_in);
    cudaGetSymbolAddress((void**)&wh,  g_w_h);
    cudaGetSymbolAddress((void**)&wl,  g_w_l);
    cudaGetSymbolAddress((void**)&qh,  g_qh);
    cudaGetSymbolAddress((void**)&kh,  g_kh);
    cudaGetSymbolAddress((void**)&vt,  g_vt);
    cudaGetSymbolAddress((void**)&ctx, g_ctx);

    float* out  = (float*)d_out;
    float* attn = out + OUT_ELEMS;
    const int write_attn =
        ((long long)out_size >= (long long)OUT_ELEMS + ATT_ELEMS) ? 1 : 0;

    cudaFuncSetAttribute(proj_gemm,
                         cudaFuncAttributeMaxDynamicSharedMemorySize, PROJ_SMEM);
    cudaFuncSetAttribute(attn_mma,
                         cudaFuncAttributeMaxDynamicSharedMemorySize, ATT_SMEM);

    convert_all<<<dim3(1024, 7), 256>>>(Q, K, V, WQ, WK, WV, WO);

    // fused Q/K/V projections
    proj_gemm<<<dim3(DD / 128, (BB * SS) / 128, 3), 256, PROJ_SMEM>>>(
        in0, in0 + 4194304, in0 + 2 * 4194304, ctx, wh, wl,
        bQ, bK, bV, bO, nullptr, qh, kh, vt, -1);

    attn_mma<<<dim3(SS / QT, HH, BB), 256, ATT_SMEM>>>(
        qh, kh, vt, ctx, attn, write_attn);

    // O projection
    proj_gemm<<<dim3(DD / 128, (BB * SS) / 128, 1), 256, PROJ_SMEM>>>(
        in0, in0 + 4194304, in0 + 2 * 4194304, ctx, wh, wl,
        bQ, bK, bV, bO, out, qh, kh, vt, 3);
}

// round 17
// speedup vs baseline: 1.6189x; 1.6189x over previous
#include <cuda_runtime.h>
#include <cuda_fp16.h>
#include <math.h>
#include <stdint.h>

#define BB 2
#define SS 2048
#define DD 1024
#define HH 16
#define DK 64
#define OUT_ELEMS (BB * SS * DD)
#define ATT_ELEMS ((long long)BB * HH * SS * (long long)SS)

// ---------------- scratch (allocation-free rule) ----------------
__device__ __align__(16) __half g_in[3][4194304];
__device__ __align__(16) __half g_w_h[4][1048576], g_w_l[4][1048576];
__device__ __align__(16) __half g_qh[4194304];
__device__ __align__(16) __half g_kh[4194304];      // K heads hi-only
__device__ __align__(16) __half g_vt[4194304];      // V^T hi-only
__device__ __align__(16) __half g_ctx[4194304];

// ---------------- PTX helpers ----------------
__device__ __forceinline__ uint32_t smem_u32(const void* p) {
    return (uint32_t)__cvta_generic_to_shared(p);
}
__device__ __forceinline__ void ldm_x4(uint32_t* r, uint32_t addr) {
    asm volatile("ldmatrix.sync.aligned.m8n8.x4.shared.b16 {%0,%1,%2,%3}, [%4];\n"
                 : "=r"(r[0]), "=r"(r[1]), "=r"(r[2]), "=r"(r[3]) : "r"(addr));
}
__device__ __forceinline__ void mma16816(float* d, const uint32_t* a,
                                         uint32_t b0, uint32_t b1) {
    asm volatile(
        "mma.sync.aligned.m16n8k16.row.col.f32.f16.f16.f32 "
        "{%0,%1,%2,%3}, {%4,%5,%6,%7}, {%8,%9}, {%0,%1,%2,%3};\n"
        : "+f"(d[0]), "+f"(d[1]), "+f"(d[2]), "+f"(d[3])
        : "r"(a[0]), "r"(a[1]), "r"(a[2]), "r"(a[3]), "r"(b0), "r"(b1));
}
__device__ __forceinline__ void split2h(float x, __half& h, __half& l) {
    h = __float2half(x);
    l = __float2half(x - __half2float(h));
}
__device__ __forceinline__ void cp16(uint32_t dst, const void* src) {
    asm volatile("cp.async.cg.shared.global [%0], [%1], 16;\n" :: "r"(dst), "l"(src));
}
__device__ __forceinline__ void cp_commit() { asm volatile("cp.async.commit_group;\n"); }
__device__ __forceinline__ void cp_wait0() { asm volatile("cp.async.wait_group 0;\n" ::: "memory"); }

// ---------------------------------------------------------------------------
// Convert fp32 sources. Inputs (A-side): fp16 plain. Weights (B-side): hi/lo.
// grid = (4096, 7).   [R15 proven]
// ---------------------------------------------------------------------------
__global__ __launch_bounds__(256) void convert_all(
    const float* __restrict__ Q, const float* __restrict__ K,
    const float* __restrict__ V, const float* __restrict__ WQ,
    const float* __restrict__ WK, const float* __restrict__ WV,
    const float* __restrict__ WO)
{
    const int seg = blockIdx.y;
    const int nf4 = (seg < 3) ? (4194304 / 4) : (1048576 / 4);
    const int i = blockIdx.x * 256 + threadIdx.x;
    if (i >= nf4) return;
    if (seg < 3) {
        const float* src = (seg == 0) ? Q : (seg == 1) ? K : V;
        __half* dh = g_in[seg];
        float4 v = ((const float4*)src)[i];
        ((__half2*)dh)[i * 2 + 0] = __floats2half2_rn(v.x, v.y);
        ((__half2*)dh)[i * 2 + 1] = __floats2half2_rn(v.z, v.w);
    } else {
        const int w = seg - 3;
        const float* src = (w == 0) ? WQ : (w == 1) ? WK : (w == 2) ? WV : WO;
        __half *dh = g_w_h[w], *dl = g_w_l[w];
        float4 v = ((const float4*)src)[i];
        __half h0, l0, h1, l1, h2, l2, h3, l3;
        split2h(v.x, h0, l0); split2h(v.y, h1, l1);
        split2h(v.z, h2, l2); split2h(v.w, h3, l3);
        ((__half2*)dh)[i * 2 + 0] = __halves2half2(h0, h1);
        ((__half2*)dh)[i * 2 + 1] = __halves2half2(h2, h3);
        ((__half2*)dl)[i * 2 + 0] = __halves2half2(l0, l1);
        ((__half2*)dl)[i * 2 + 1] = __halves2half2(l2, l3);
    }
}

// ---------------------------------------------------------------------------
// Projection GEMM: out = A @ B^T + bias. A plain fp16, B hi/lo fp16.
// BK=64, 2-stage cp.async, 128x128 tile, 8 warps (4m x 2n). [R15 proven]
// z: 0=Q (scaled, hi-only), 1=K (hi-only), 2=V (V^T hi-only), 3=O (fp32).
// ---------------------------------------------------------------------------
#define PPAD 72
#define PTILE (128 * PPAD)
#define PSTAGE (3 * PTILE)
#define PROJ_SMEM (2 * PSTAGE * (int)sizeof(__half))  // 110592

__device__ __forceinline__ void proj_issue(
    __half* ps, int stage,
    const __half* A_, const __half* Bh_, const __half* Bl_,
    int bm, int bn, int kt, int tid)
{
    __half* base = ps + stage * PSTAGE;
#pragma unroll
    for (int t = 0; t < 12; t++) {
        const int idx = tid + t * 256;
        const int arr = idx >> 10;
        const int row = (idx >> 3) & 127;
        const int ch = idx & 7;
        const __half* g;
        if (arr == 0)      g = A_  + (size_t)(bm * 128 + row) * 1024 + kt + ch * 8;
        else if (arr == 1) g = Bh_ + (size_t)(bn * 128 + row) * 1024 + kt + ch * 8;
        else               g = Bl_ + (size_t)(bn * 128 + row) * 1024 + kt + ch * 8;
        cp16(smem_u32(base + arr * PTILE + row * PPAD + ch * 8), g);
    }
    cp_commit();
}

__global__ __launch_bounds__(256, 2) void proj_gemm(
    const __half* __restrict__ in0, const __half* __restrict__ in1,
    const __half* __restrict__ in2, const __half* __restrict__ ctx,
    const __half* __restrict__ wh, const __half* __restrict__ wl,
    const float* __restrict__ bQ, const float* __restrict__ bK,
    const float* __restrict__ bV, const float* __restrict__ bO,
    float* __restrict__ outO,
    __half* __restrict__ qh, __half* __restrict__ kh,
    __half* __restrict__ vt,
    int which)
{
    extern __shared__ __half ps[];
    const int tid = threadIdx.x, lane = tid & 31, wid = tid >> 5;
    const int wm = wid >> 1, wn = wid & 1;
    const int bm = blockIdx.y, bn = blockIdx.x;
    const int z = (which >= 0) ? which : (int)blockIdx.z;

    const __half *A_, *Bh_, *Bl_;
    const float* bias;
    __half* oh = nullptr;
    int mode; float scale = 1.0f;
    if (z == 0)      { A_ = in0; Bh_ = wh; Bl_ = wl; bias = bQ; mode = 1;
                       oh = qh; scale = 0.125f * 1.4426950408889634f; }
    else if (z == 1) { A_ = in1; Bh_ = wh + 1048576; Bl_ = wl + 1048576;
                       bias = bK; mode = 1; oh = kh; }
    else if (z == 2) { A_ = in2; Bh_ = wh + 2 * 1048576; Bl_ = wl + 2 * 1048576;
                       bias = bV; mode = 3; }
    else             { A_ = ctx; Bh_ = wh + 3 * 1048576; Bl_ = wl + 3 * 1048576;
                       bias = bO; mode = 0; }

    float acc[2][8][4];
#pragma unroll
    for (int m = 0; m < 2; m++)
#pragma unroll
        for (int n = 0; n < 8; n++)
#pragma unroll
            for (int k = 0; k < 4; k++) acc[m][n][k] = 0.0f;

    proj_issue(ps, 0, A_, Bh_, Bl_, bm, bn, 0, tid);

    for (int kt = 0; kt < 1024; kt += 64) {
        const int s = (kt >> 6) & 1;
        cp_wait0();
        __syncthreads();
        if (kt + 64 < 1024)
            proj_issue(ps, s ^ 1, A_, Bh_, Bl_, bm, bn, kt + 64, tid);

        __half* Ah = ps + s * PSTAGE;
        __half* Bh = Ah + PTILE;
        __half* Bl = Bh + PTILE;

#pragma unroll
        for (int kk = 0; kk < 64; kk += 16) {
            uint32_t ah[2][4];
#pragma unroll
            for (int mt = 0; mt < 2; mt++) {
                const int r = wm * 32 + mt * 16 + (lane & 15);
                const int c = kk + (lane >> 4) * 8;
                ldm_x4(ah[mt], smem_u32(&Ah[r * PPAD + c]));
            }
#pragma unroll
            for (int nt = 0; nt < 4; nt++) {
                uint32_t bh[4], bl[4];
                const int r = wn * 64 + nt * 16 + (lane & 15);
                const int c = kk + (lane >> 4) * 8;
                ldm_x4(bh, smem_u32(&Bh[r * PPAD + c]));
                ldm_x4(bl, smem_u32(&Bl[r * PPAD + c]));
#pragma unroll
                for (int mt = 0; mt < 2; mt++) {
                    mma16816(acc[mt][nt * 2 + 0], ah[mt], bh[0], bh[2]);
                    mma16816(acc[mt][nt * 2 + 1], ah[mt], bh[1], bh[3]);
                    mma16816(acc[mt][nt * 2 + 0], ah[mt], bl[0], bl[2]);
                    mma16816(acc[mt][nt * 2 + 1], ah[mt], bl[1], bl[3]);
                }
            }
        }
    }

#pragma unroll
    for (int mt = 0; mt < 2; mt++) {
#pragma unroll
        for (int n8 = 0; n8 < 8; n8++) {
            const int r0 = bm * 128 + wm * 32 + mt * 16 + (lane >> 2);
            const int c  = bn * 128 + wn * 64 + n8 * 8 + (lane & 3) * 2;
            const float b0 = bias[c], b1 = bias[c + 1];
#pragma unroll
            for (int half_ = 0; half_ < 2; half_++) {
                const int r = r0 + half_ * 8;
                const float v0 = (acc[mt][n8][half_ * 2 + 0] + b0) * scale;
                const float v1 = (acc[mt][n8][half_ * 2 + 1] + b1) * scale;
                const int bb = r >> 11, sidx = r & 2047;
                const int hh = c >> 6, dk = c & 63;
                if (mode == 0) {
                    *(float2*)&outO[(size_t)r * DD + c] = make_float2(v0, v1);
                } else if (mode == 1) {
                    const size_t a = ((size_t)(bb * HH + hh) * SS + sidx) * DK + dk;
                    *(__half2*)&oh[a] = __floats2half2_rn(v0, v1);
                } else {
                    const size_t a = ((size_t)(bb * HH + hh) * DK + dk) * SS + sidx;
                    vt[a] = __float2half(v0);
                    vt[a + SS] = __float2half(v1);
                }
            }
        }
    }
}

// ---------------------------------------------------------------------------
// Attention (R15 proven body): q-tile 128, 256 threads, two-pass, hi-only
// scores + hi-only V, P in registers. 1-D grid with GLOBAL longest-first:
// blocks 0..31 are the longest q-tile across all (h,b), etc.
// ---------------------------------------------------------------------------
#define QT 128
#define APAD 72
#define ATILE (64 * APAD)
#define ATT_SMEM (10 * ATILE * (int)sizeof(__half) + 256)  // 92416

// pass B: Kh -> slot0, Vh -> slot2
__device__ __forceinline__ void attn_issueKV(
    __half* sm, int stage,
    const __half* Kh_, const __half* Vt_,
    int bh, int k0, int tid)
{
    __half* base = sm + stage * 4 * ATILE;
#pragma unroll
    for (int t = 0; t < 4; t++) {
        const int idx = tid + t * 256;
        const int arr = idx >> 9, row = (idx >> 3) & 63, ch = idx & 7;
        const __half* g;
        int slot;
        if (arr == 0) { g = Kh_ + ((size_t)bh * SS + k0 + row) * DK + ch * 8; slot = 0; }
        else          { g = Vt_ + ((size_t)bh * DK + row) * SS + k0 + ch * 8; slot = 2; }
        cp16(smem_u32(base + slot * ATILE + row * APAD + ch * 8), g);
    }
    cp_commit();
}

// pass A: Kh only
__device__ __forceinline__ void attn_issueKh(
    __half* sm, int stage,
    const __half* Kh_,
    int bh, int k0, int tid)
{
    __half* base = sm + stage * 4 * ATILE;
#pragma unroll
    for (int t = 0; t < 2; t++) {
        const int idx = tid + t * 256;
        const int row = (idx >> 3) & 63, ch = idx & 7;
        const __half* g = Kh_ + ((size_t)bh * SS + k0 + row) * DK + ch * 8;
        cp16(smem_u32(base + row * APAD + ch * 8), g);
    }
    cp_commit();
}

__global__ __launch_bounds__(256, 2) void attn_mma(
    const __half* __restrict__ Qh_,
    const __half* __restrict__ Kh_,
    const __half* __restrict__ Vt_,
    __half* __restrict__ ctx,
    float* __restrict__ attn_out, int write_attn)
{
    extern __shared__ __half sm[];
    __half* Ph = sm + 8 * ATILE;   // Q staging only

    const int tid = threadIdx.x, lane = tid & 31, wid = tid >> 5;
    // global longest-first: qtile-major, (h,b) minor
    const int qtile = (int)blockIdx.x >> 5;          // 0..15, 0 = longest
    const int hb = (int)blockIdx.x & 31;
    const int b = hb >> 4, h = hb & 15, bh = b * HH + h;
    const int q0 = (SS / QT - 1 - qtile) * QT;

    // ---- prologue: Q tile (hi only) -> Ph, K tile 0 -> stage 0 ----
#pragma unroll
    for (int t = 0; t < 4; t++) {
        const int idx = tid + t * 256;
        const int row = (idx >> 3) & 127, ch = idx & 7;
        const __half* g = Qh_ + ((size_t)bh * SS + q0 + row) * DK + ch * 8;
        cp16(smem_u32(Ph + row * APAD + ch * 8), g);
    }
    cp_commit();
    attn_issueKh(sm, 0, Kh_, bh, 0, tid);
    cp_wait0();
    __syncthreads();

    uint32_t qf[4][4];
#pragma unroll
    for (int kk = 0; kk < 4; kk++) {
        const int r = wid * 16 + (lane & 15);
        const int c = kk * 16 + (lane >> 4) * 8;
        ldm_x4(qf[kk], smem_u32(&Ph[r * APAD + c]));
    }
    __syncthreads();

    const int qr0 = q0 + wid * 16 + (lane >> 2);
    const int qmaxw = q0 + wid * 16 + 15;
    const int kend = q0 + 64;
    float lacc0 = 0.0f, lacc1 = 0.0f;

    // ================= PASS A: row sums (K-hi only) =================
    for (int k0 = 0; k0 <= kend; k0 += 64) {
        const int s = (k0 >> 6) & 1;
        cp_wait0();
        __syncthreads();
        if (k0 + 64 <= kend)
            attn_issueKh(sm, s ^ 1, Kh_, bh, k0 + 64, tid);

        if (k0 <= qmaxw) {
            __half* Kh = sm + s * 4 * ATILE;

            float sa[8][4];
#pragma unroll
            for (int f = 0; f < 8; f++)
#pragma unroll
                for (int k = 0; k < 4; k++) sa[f][k] = 0.0f;

#pragma unroll
            for (int kk = 0; kk < 4; kk++) {
#pragma unroll
                for (int nt = 0; nt < 4; nt++) {
                    uint32_t bhf[4];
                    const int r = nt * 16 + (lane & 15);
                    const int c = kk * 16 + (lane >> 4) * 8;
                    ldm_x4(bhf, smem_u32(&Kh[r * APAD + c]));
                    mma16816(sa[nt * 2 + 0], qf[kk], bhf[0], bhf[2]);
                    mma16816(sa[nt * 2 + 1], qf[kk], bhf[1], bhf[3]);
                }
            }

            const bool diag = (k0 + 63 > q0 + wid * 16);
#pragma unroll
            for (int f = 0; f < 8; f++) {
                const int jc = k0 + (f >> 1) * 16 + (f & 1) * 8 + (lane & 3) * 2;
#pragma unroll
                for (int half_ = 0; half_ < 2; half_++) {
                    const int qr = qr0 + half_ * 8;
                    float p0 = exp2f(sa[f][half_ * 2 + 0]);
                    float p1 = exp2f(sa[f][half_ * 2 + 1]);
                    if (diag) {
                        if (jc + 0 > qr) p0 = 0.0f;
                        if (jc + 1 > qr) p1 = 0.0f;
                    }
                    if (half_ == 0) lacc0 += p0 + p1; else lacc1 += p0 + p1;
                }
            }
        }
    }

    lacc0 += __shfl_xor_sync(0xffffffffu, lacc0, 1);
    lacc0 += __shfl_xor_sync(0xffffffffu, lacc0, 2);
    lacc1 += __shfl_xor_sync(0xffffffffu, lacc1, 1);
    lacc1 += __shfl_xor_sync(0xffffffffu, lacc1, 2);
    const float inv0 = 1.0f / lacc0;
    const float inv1 = 1.0f / lacc1;

    float ctxa[8][4];
#pragma unroll
    for (int f = 0; f < 8; f++)
#pragma unroll
        for (int k = 0; k < 4; k++) ctxa[f][k] = 0.0f;

    // ================= PASS B: normalized attn + PV (P in regs, V hi) =======
    cp_wait0();
    __syncthreads();
    attn_issueKV(sm, 0, Kh_, Vt_, bh, 0, tid);

    for (int k0 = 0; k0 <= kend; k0 += 64) {
        const int s = (k0 >> 6) & 1;
        cp_wait0();
        __syncthreads();
        if (k0 + 64 <= kend)
            attn_issueKV(sm, s ^ 1, Kh_, Vt_, bh, k0 + 64, tid);

        if (k0 > qmaxw) {
            if (write_attn) {
#pragma unroll
                for (int f = 0; f < 8; f++) {
                    const int jc = k0 + (f >> 1) * 16 + (f & 1) * 8 + (lane & 3) * 2;
#pragma unroll
                    for (int half_ = 0; half_ < 2; half_++) {
                        const int qr = qr0 + half_ * 8;
                        const size_t grow = (size_t)(bh * SS + qr);
                        *(float2*)&attn_out[grow * SS + jc] = make_float2(0.f, 0.f);
                    }
                }
            }
            continue;
        }

        __half* Kh = sm + s * 4 * ATILE;
        __half* Vh = Kh + 2 * ATILE;

        float sa[8][4];
#pragma unroll
        for (int f = 0; f < 8; f++)
#pragma unroll
            for (int k = 0; k < 4; k++) sa[f][k] = 0.0f;

#pragma unroll
        for (int kk = 0; kk < 4; kk++) {
#pragma unroll
            for (int nt = 0; nt < 4; nt++) {
                uint32_t bhf[4];
                const int r = nt * 16 + (lane & 15);
                const int c = kk * 16 + (lane >> 4) * 8;
                ldm_x4(bhf, smem_u32(&Kh[r * APAD + c]));
                mma16816(sa[nt * 2 + 0], qf[kk], bhf[0], bhf[2]);
                mma16816(sa[nt * 2 + 1], qf[kk], bhf[1], bhf[3]);
            }
        }

        const bool diag = (k0 + 63 > q0 + wid * 16);
        uint32_t pa[4][4];   // [kk][a-reg] A-fragment of P
#pragma unroll
        for (int f = 0; f < 8; f++) {
            const int jc = k0 + (f >> 1) * 16 + (f & 1) * 8 + (lane & 3) * 2;
#pragma unroll
            for (int half_ = 0; half_ < 2; half_++) {
                const int qr = qr0 + half_ * 8;
                const float iv = half_ ? inv1 : inv0;
                float p0 = exp2f(sa[f][half_ * 2 + 0]) * iv;
                float p1 = exp2f(sa[f][half_ * 2 + 1]) * iv;
                if (diag) {
                    if (jc + 0 > qr) p0 = 0.0f;
                    if (jc + 1 > qr) p1 = 0.0f;
                }
                if (write_attn) {
                    const size_t grow = (size_t)(bh * SS + qr);
                    *(float2*)&attn_out[grow * SS + jc] = make_float2(p0, p1);
                }
                __half2 ph2 = __floats2half2_rn(p0, p1);
                pa[f >> 1][(f & 1) * 2 + half_] = *(uint32_t*)&ph2;
            }
        }

        // ---- ctx += P V (V hi-only) ----
#pragma unroll
        for (int kk = 0; kk < 4; kk++) {
#pragma unroll
            for (int nt = 0; nt < 4; nt++) {
                uint32_t vh_[4];
                const int r = nt * 16 + (lane & 15);
                const int c = kk * 16 + (lane >> 4) * 8;
                ldm_x4(vh_, smem_u32(&Vh[r * APAD + c]));
                mma16816(ctxa[nt * 2 + 0], pa[kk], vh_[0], vh_[2]);
                mma16816(ctxa[nt * 2 + 1], pa[kk], vh_[1], vh_[3]);
            }
        }
    }

    // ---- ctx write (concat layout), plain fp16 ----
    const int qloc = wid * 16 + (lane >> 2);
#pragma unroll
    for (int f = 0; f < 8; f++) {
        const int dc = (f >> 1) * 16 + (f & 1) * 8 + (lane & 3) * 2;
        const size_t r0 = (size_t)(b * SS + q0 + qloc);
        *(__half2*)&ctx[r0 * DD + h * DK + dc] =
            __floats2half2_rn(ctxa[f][0], ctxa[f][1]);
        *(__half2*)&ctx[(r0 + 8) * DD + h * DK + dc] =
            __floats2half2_rn(ctxa[f][2], ctxa[f][3]);
    }

    // ---- zero-fill columns [q0+QT, SS) for these QT rows ----
    if (write_attn) {
        const int zstart = q0 + QT;
        const int zw = SS - zstart;
        if (zw > 0) {
            const int n4 = zw >> 2;
            const size_t base = (size_t)bh * SS * SS;
            const float4 z = make_float4(0.f, 0.f, 0.f, 0.f);
            for (int i = tid; i < QT * n4; i += 256) {
                const int r = i / n4;
                const int cc = (i - r * n4) << 2;
                *(float4*)&attn_out[base + (size_t)(q0 + r) * SS + zstart + cc] = z;
            }
        }
    }
}

// ---------------------------------------------------------------------------
extern "C" void kernel_launch(void* const* d_in, const int* in_sizes, int n_in,
                              void* d_out, int out_size)
{
    const float* Q  = (const float*)d_in[0];
    const float* K  = (const float*)d_in[1];
    const float* V  = (const float*)d_in[2];
    // d_in[3] = causal mask (fixed) — handled analytically
    const float* WQ = (const float*)d_in[4];
    const float* bQ = (const float*)d_in[5];
    const float* WK = (const float*)d_in[6];
    const float* bK = (const float*)d_in[7];
    const float* WV = (const float*)d_in[8];
    const float* bV = (const float*)d_in[9];
    const float* WO = (const float*)d_in[10];
    const float* bO = (const float*)d_in[11];

    __half *in0, *wh, *wl, *qh, *kh, *vt, *ctx;
    cudaGetSymbolAddress((void**)&in0, g_in);
    cudaGetSymbolAddress((void**)&wh,  g_w_h);
    cudaGetSymbolAddress((void**)&wl,  g_w_l);
    cudaGetSymbolAddress((void**)&qh,  g_qh);
    cudaGetSymbolAddress((void**)&kh,  g_kh);
    cudaGetSymbolAddress((void**)&vt,  g_vt);
    cudaGetSymbolAddress((void**)&ctx, g_ctx);

    float* out  = (float*)d_out;
    float* attn = out + OUT_ELEMS;
    const int write_attn =
        ((long long)out_size >= (long long)OUT_ELEMS + ATT_ELEMS) ? 1 : 0;

    cudaFuncSetAttribute(proj_gemm,
                         cudaFuncAttributeMaxDynamicSharedMemorySize, PROJ_SMEM);
    cudaFuncSetAttribute(attn_mma,
                         cudaFuncAttributeMaxDynamicSharedMemorySize, ATT_SMEM);

    convert_all<<<dim3(4096, 7), 256>>>(Q, K, V, WQ, WK, WV, WO);

    // fused Q/K/V projections
    proj_gemm<<<dim3(DD / 128, (BB * SS) / 128, 3), 256, PROJ_SMEM>>>(
        in0, in0 + 4194304, in0 + 2 * 4194304, ctx, wh, wl,
        bQ, bK, bV, bO, nullptr, qh, kh, vt, -1);

    // 1-D grid, global longest-first
    attn_mma<<<(SS / QT) * HH * BB, 256, ATT_SMEM>>>(
        qh, kh, vt, ctx, attn, write_attn);

    // O projection
    proj_gemm<<<dim3(DD / 128, (BB * SS) / 128, 1), 256, PROJ_SMEM>>>(
        in0, in0 + 4194304, in0 + 2 * 4194304, ctx, wh, wl,
        bQ, bK, bV, bO, out, qh, kh, vt, 3);
}